// round 7
// baseline (speedup 1.0000x reference)
#include <cuda_runtime.h>
#include <cooperative_groups.h>
#include <cstdint>

namespace cg = cooperative_groups;

#define Bb 128
#define Tt 1024
#define Dd 256
#define Hh 256
#define Gg 1024  // 4H

typedef unsigned long long ull;

// 512 MB scratch for xg = x @ Wi
__device__ float g_xg[(size_t)Bb * Tt * Gg];

// ---- packed fp32x2 helpers (SASS FFMA2 — only reachable via PTX) ----
#define FMA2(d, a, b) \
  asm("fma.rn.f32x2 %0, %1, %2, %0;" : "+l"(d) : "l"(a), "l"(b))

__device__ __forceinline__ ull pack_dup(float x) {
  ull d;
  unsigned u = __float_as_uint(x);
  asm("mov.b64 %0, {%1, %1};" : "=l"(d) : "r"(u));
  return d;
}
__device__ __forceinline__ ull pack2(float a, float b) {
  ull d;
  asm("mov.b64 %0, {%1, %2};" : "=l"(d) : "f"(a), "f"(b));
  return d;
}
__device__ __forceinline__ float2 unpack2(ull v) {
  float2 r;
  asm("mov.b64 {%0, %1}, %2;" : "=f"(r.x), "=f"(r.y) : "l"(v));
  return r;
}

// ---------------------------------------------------------------------------
// Kernel A: xg[m, g] = sum_d x[m, d] * Wi[d, g]   (M=131072, N=1024, K=256)
// (unchanged from round 5 — FFMA2 microtile SGEMM)
// ---------------------------------------------------------------------------
__global__ __launch_bounds__(256, 2) void xg_gemm(const float* __restrict__ X,
                                                  const float* __restrict__ Wi) {
  __shared__ float As[16][132];
  __shared__ float Bs[16][128];

  const int tid = threadIdx.x;
  const size_t mbase = (size_t)blockIdx.y * 128;
  const int nbase = blockIdx.x * 128;
  const float* A0 = X + mbase * Dd;
  const float* B0 = Wi + nbase;

  const int arow = tid >> 2;
  const int acol = (tid & 3) << 2;
  const int brow = tid >> 5;
  const int bcol = (tid & 31) << 2;
  const int tx = tid & 15;
  const int ty = tid >> 4;

  ull acc[8][4];
#pragma unroll
  for (int i = 0; i < 8; i++)
#pragma unroll
    for (int j = 0; j < 4; j++) acc[i][j] = 0ull;

  for (int k0 = 0; k0 < Dd; k0 += 16) {
#pragma unroll
    for (int i = 0; i < 2; i++) {
      float4 a = *(const float4*)(A0 + (size_t)(arow + i * 64) * Dd + k0 + acol);
      As[acol + 0][arow + i * 64] = a.x;
      As[acol + 1][arow + i * 64] = a.y;
      As[acol + 2][arow + i * 64] = a.z;
      As[acol + 3][arow + i * 64] = a.w;
    }
#pragma unroll
    for (int i = 0; i < 2; i++) {
      *(float4*)&Bs[brow + i * 8][bcol] =
          *(const float4*)(B0 + (size_t)(k0 + brow + i * 8) * Gg + bcol);
    }
    __syncthreads();
#pragma unroll
    for (int k = 0; k < 16; k++) {
      float ra[8];
      *(float4*)&ra[0] = *(const float4*)&As[k][ty * 8];
      *(float4*)&ra[4] = *(const float4*)&As[k][ty * 8 + 4];
      ulonglong2 rb0 = *(const ulonglong2*)&Bs[k][tx * 8];
      ulonglong2 rb1 = *(const ulonglong2*)&Bs[k][tx * 8 + 4];
      ull ra2[8];
#pragma unroll
      for (int i = 0; i < 8; i++) ra2[i] = pack_dup(ra[i]);
#pragma unroll
      for (int i = 0; i < 8; i++) {
        FMA2(acc[i][0], ra2[i], rb0.x);
        FMA2(acc[i][1], ra2[i], rb0.y);
        FMA2(acc[i][2], ra2[i], rb1.x);
        FMA2(acc[i][3], ra2[i], rb1.y);
      }
    }
    __syncthreads();
  }

  float* C = g_xg + (mbase + (size_t)ty * 8) * Gg + nbase + tx * 8;
#pragma unroll
  for (int i = 0; i < 8; i++) {
    float2 p0 = unpack2(acc[i][0]);
    float2 p1 = unpack2(acc[i][1]);
    float2 p2 = unpack2(acc[i][2]);
    float2 p3 = unpack2(acc[i][3]);
    *(float4*)(C + (size_t)i * Gg) = make_float4(p0.x, p0.y, p1.x, p1.y);
    *(float4*)(C + (size_t)i * Gg + 4) = make_float4(p2.x, p2.y, p3.x, p3.y);
  }
}

// ---------------------------------------------------------------------------
// Kernel B: persistent cluster LSTM recurrence, mbarrier + st.async sync.
// 16 clusters x 8 CTAs, 256 threads. CTA r owns gate cols {g*256+r*32..+32}.
// h for step t lives in buffer (t&1), guarded by mbar[t&1] (expect 8192 B).
// End of step t: 128 threads push float2 h-slices to all 8 ranks via
// st.async.b64 with complete_tx on the target's mbar[(t+1)&1].
// ---------------------------------------------------------------------------

// SMEM float offsets
#define WHS_OFF 0        // [64 kc][128 col][4]   = 32768
#define HB_OFF 32768     // [2][8 b][256 k]       =  4096
#define PART_OFF 36864   // [2 ks][8 b][128 col]  =  2048
#define XGS_OFF 38912    // [2][8 b][128 col]     =  2048
#define SMEM_FLOATS 40960
#define MB_BYTE (SMEM_FLOATS * 4)           // 2 mbarriers (16 B)
#define SMEM_BYTES (MB_BYTE + 16)

__device__ __forceinline__ void mbar_init_(uint32_t a, uint32_t cnt) {
  asm volatile("mbarrier.init.shared.b64 [%0], %1;" ::"r"(a), "r"(cnt)
               : "memory");
}
__device__ __forceinline__ void mbar_expect_tx(uint32_t a, uint32_t tx) {
  asm volatile("mbarrier.arrive.expect_tx.shared.b64 _, [%0], %1;" ::"r"(a),
               "r"(tx)
               : "memory");
}
__device__ __forceinline__ void mbar_wait_cluster(uint32_t mbar,
                                                  uint32_t parity) {
  asm volatile(
      "{\n\t"
      ".reg .pred P;\n\t"
      "WL_%=:\n\t"
      "mbarrier.try_wait.parity.acquire.cluster.shared::cta.b64 P, [%0], %1, 0x989680;\n\t"
      "@P bra.uni WD_%=;\n\t"
      "bra.uni WL_%=;\n\t"
      "WD_%=:\n\t"
      "}" ::"r"(mbar),
      "r"(parity)
      : "memory");
}
__device__ __forceinline__ uint32_t mapa_u32(uint32_t la, int rk) {
  uint32_t ra;
  asm("mapa.shared::cluster.u32 %0, %1, %2;" : "=r"(ra) : "r"(la), "r"(rk));
  return ra;
}
__device__ __forceinline__ void st_async_b64(uint32_t raddr, ull v,
                                             uint32_t rmbar) {
  asm volatile(
      "st.async.shared::cluster.mbarrier::complete_tx::bytes.b64 [%0], %1, [%2];" ::
          "r"(raddr),
      "l"(v), "r"(rmbar)
      : "memory");
}

__device__ __forceinline__ float sigf(float x) {
  return 1.f / (1.f + __expf(-x));
}
__device__ __forceinline__ float tanhf_(float x) {
  return 2.f / (1.f + __expf(-2.f * x)) - 1.f;
}

__device__ __forceinline__ void prefetch_xg(float* dst, int cl, int r, int t,
                                            int tid) {
  int b = tid >> 5;
  int rem = tid & 31;
  int g = rem >> 3;
  int sub = rem & 7;
  size_t src = ((size_t)(cl * 8 + b) * Tt + t) * Gg + (g << 8) + (r << 5) +
               (sub << 2);
  unsigned saddr =
      (unsigned)__cvta_generic_to_shared(dst + (b << 7) + (g << 5) + (sub << 2));
  asm volatile("cp.async.cg.shared.global [%0], [%1], 16;\n" ::"r"(saddr),
               "l"(g_xg + src));
}

__global__ __launch_bounds__(256, 1) __cluster_dims__(8, 1, 1)
void lstm_rec(const float* __restrict__ Wh, const float* __restrict__ bh,
              float* __restrict__ out) {
  extern __shared__ float sm[];
  float* whs = sm + WHS_OFF;
  float* hb = sm + HB_OFF;
  float* part = sm + PART_OFF;
  float* xgs = sm + XGS_OFF;

  cg::cluster_group cluster = cg::this_cluster();
  const int r = blockIdx.x;
  const int cl = blockIdx.y;
  const int tid = threadIdx.x;
  const uint32_t smb = (uint32_t)__cvta_generic_to_shared(sm);

  // ---- one-time init ----
  for (int idx = tid; idx < 32768; idx += 256) {
    int c = idx & 127;
    int k = idx >> 7;
    int gcol = ((c >> 5) << 8) + (r << 5) + (c & 31);
    whs[((k >> 2) << 9) + (c << 2) + (k & 3)] = Wh[k * Gg + gcol];
  }
  for (int idx = tid; idx < 4096; idx += 256) hb[idx] = 0.f;

  if (tid == 0) {
    mbar_init_(smb + MB_BYTE, 1);
    mbar_init_(smb + MB_BYTE + 8, 1);
    mbar_expect_tx(smb + MB_BYTE, 8192);
    mbar_expect_tx(smb + MB_BYTE + 8, 8192);
  }

  // bias regs for update mapping (b = tid>>4, cols j2, j2+1 per gate)
  const int ub = tid >> 4;
  const int j2 = (tid & 15) << 1;
  float breg[8];
#pragma unroll
  for (int g = 0; g < 4; g++) {
    breg[2 * g] = bh[(g << 8) + (r << 5) + j2];
    breg[2 * g + 1] = bh[(g << 8) + (r << 5) + j2 + 1];
  }

  uint32_t rank_base[8];
#pragma unroll
  for (int rk = 0; rk < 8; rk++) rank_base[rk] = mapa_u32(smb, rk);

  prefetch_xg(xgs, cl, r, 0, tid);
  asm volatile("cp.async.commit_group;" ::: "memory");

  cluster.sync();  // mbarriers + smem init visible before any st.async

  // GEMM mapping: 2-way k-split, one col x 8 batches per thread
  const int ks = tid >> 7;  // 0..1
  const int col = tid & 127;
  const int kc0 = ks << 5;

  float c0r = 0.f, c1r = 0.f;
  int ph0 = 0, ph1 = 0;
  const size_t OUT_FIN = (size_t)Bb * Tt * Hh;
  const int m0 = (r << 5) + j2;
  const size_t gb = (size_t)(cl << 3) + ub;
  float* const out_base = out + (gb << 10) * Hh + m0;

  for (int t = 0; t < Tt; t++) {
    if (t) {
      int q = t & 1;
      uint32_t mb = smb + MB_BYTE + (q << 3);
      mbar_wait_cluster(mb, q ? ph1 : ph0);
      if (q) ph1 ^= 1; else ph0 ^= 1;
      if (tid == 0) mbar_expect_tx(mb, 8192);  // re-arm next phase
    }
    __syncthreads();  // part[] WAR + re-arm ordered before our pushes

    if (t + 1 < Tt) prefetch_xg(xgs + ((t + 1) & 1) * 1024, cl, r, t + 1, tid);
    asm volatile("cp.async.commit_group;" ::: "memory");

    // ---- GEMM: part[ks][b][col] = sum_{k in half ks} h[b][k]*Wh[k][col] ----
    {
      const ulonglong2* w2 = (const ulonglong2*)whs;
      const ulonglong2* h2 = (const ulonglong2*)(hb + (t & 1) * 2048);
      ull acc[8];
#pragma unroll
      for (int b = 0; b < 8; b++) acc[b] = 0ull;
#pragma unroll 8
      for (int kk = 0; kk < 32; kk++) {
        int kc = kc0 + kk;
        ulonglong2 wv = w2[(kc << 7) + col];
#pragma unroll
        for (int b = 0; b < 8; b++) {
          ulonglong2 hv = h2[(b << 6) + kc];
          FMA2(acc[b], hv.x, wv.x);
          FMA2(acc[b], hv.y, wv.y);
        }
      }
#pragma unroll
      for (int b = 0; b < 8; b++) {
        float2 s = unpack2(acc[b]);
        part[(ks << 10) + (b << 7) + col] = s.x + s.y;
      }
    }

    asm volatile("cp.async.wait_group 1;" ::: "memory");
    __syncthreads();

    // ---- update: 128 threads, 2 adjacent cols each ----
    if (tid < 128) {
      const float* pc = part + (ub << 7);
      const float* xc = xgs + (t & 1) * 1024 + (ub << 7);
      float gi0 = pc[j2] + pc[1024 + j2] + xc[j2] + breg[0];
      float gi1 = pc[j2 + 1] + pc[1024 + j2 + 1] + xc[j2 + 1] + breg[1];
      float gf0 = pc[32 + j2] + pc[1056 + j2] + xc[32 + j2] + breg[2];
      float gf1 = pc[33 + j2] + pc[1057 + j2] + xc[33 + j2] + breg[3];
      float gg0 = pc[64 + j2] + pc[1088 + j2] + xc[64 + j2] + breg[4];
      float gg1 = pc[65 + j2] + pc[1089 + j2] + xc[65 + j2] + breg[5];
      float go0 = pc[96 + j2] + pc[1120 + j2] + xc[96 + j2] + breg[6];
      float go1 = pc[97 + j2] + pc[1121 + j2] + xc[97 + j2] + breg[7];

      float i0 = sigf(gi0), i1 = sigf(gi1);
      float f0 = sigf(gf0), f1 = sigf(gf1);
      float z0 = tanhf_(gg0), z1 = tanhf_(gg1);
      float o0 = sigf(go0), o1 = sigf(go1);
      c0r = f0 * c0r + i0 * z0;
      c1r = f1 * c1r + i1 * z1;
      float hv0 = o0 * tanhf_(c0r);
      float hv1 = o1 * tanhf_(c1r);

      if (t + 1 < Tt) {
        ull pk = pack2(hv0, hv1);
        int qn = (t + 1) & 1;
        uint32_t doff = (uint32_t)((HB_OFF + qn * 2048 + (ub << 8) + m0) << 2);
        uint32_t moff = (uint32_t)(MB_BYTE + (qn << 3));
#pragma unroll
        for (int i = 0; i < 8; i++) {
          int rk = (i + (tid & 7)) & 7;  // stagger fabric traffic
          st_async_b64(rank_base[rk] + doff, pk, rank_base[rk] + moff);
        }
      }

      // global stores (off the sync path)
      *(float2*)(out_base + (size_t)t * Hh) = make_float2(hv0, hv1);
      if (t == Tt - 1) {
        *(float2*)(out + OUT_FIN + gb * Hh + m0) = make_float2(c0r, c1r);
        *(float2*)(out + OUT_FIN + (size_t)Bb * Hh + gb * Hh + m0) =
            make_float2(hv0, hv1);
      }
    }
  }

  cluster.sync();  // no CTA exits while peer traffic could be in flight
}

// ---------------------------------------------------------------------------
extern "C" void kernel_launch(void* const* d_in, const int* in_sizes, int n_in,
                              void* d_out, int out_size) {
  const float* x = (const float*)d_in[0];    // [B, T, D]
  const float* Wi = (const float*)d_in[1];   // [D, 4H]
  const float* Wh = (const float*)d_in[2];   // [H, 4H]
  const float* bh = (const float*)d_in[3];   // [4H]
  float* out = (float*)d_out;                // outputs | c_fin | h_fin

  dim3 gA(Gg / 128, (Bb * Tt) / 128);  // (8, 1024)
  xg_gemm<<<gA, 256>>>(x, Wi);

  cudaFuncSetAttribute(lstm_rec, cudaFuncAttributeMaxDynamicSharedMemorySize,
                       SMEM_BYTES);
  lstm_rec<<<dim3(8, 16), 256, SMEM_BYTES>>>(Wh, bh, out);
}

// round 8
// speedup vs baseline: 1.0325x; 1.0325x over previous
#include <cuda_runtime.h>
#include <cooperative_groups.h>
#include <cstdint>

namespace cg = cooperative_groups;

#define Bb 128
#define Tt 1024
#define Dd 256
#define Hh 256
#define Gg 1024  // 4H

typedef unsigned long long ull;

// 512 MB scratch for xg = x @ Wi
__device__ float g_xg[(size_t)Bb * Tt * Gg];

// ---- packed fp32x2 helpers (SASS FFMA2 — only reachable via PTX) ----
#define FMA2(d, a, b) \
  asm("fma.rn.f32x2 %0, %1, %2, %0;" : "+l"(d) : "l"(a), "l"(b))

__device__ __forceinline__ ull pack_dup(float x) {
  ull d;
  unsigned u = __float_as_uint(x);
  asm("mov.b64 %0, {%1, %1};" : "=l"(d) : "r"(u));
  return d;
}
__device__ __forceinline__ float2 unpack2(ull v) {
  float2 r;
  asm("mov.b64 {%0, %1}, %2;" : "=f"(r.x), "=f"(r.y) : "l"(v));
  return r;
}

// ---------------------------------------------------------------------------
// Kernel A: xg[m, g] = sum_d x[m, d] * Wi[d, g]   (M=131072, N=1024, K=256)
// (unchanged — FFMA2 microtile SGEMM, proven passing)
// ---------------------------------------------------------------------------
__global__ __launch_bounds__(256, 2) void xg_gemm(const float* __restrict__ X,
                                                  const float* __restrict__ Wi) {
  __shared__ float As[16][132];
  __shared__ float Bs[16][128];

  const int tid = threadIdx.x;
  const size_t mbase = (size_t)blockIdx.y * 128;
  const int nbase = blockIdx.x * 128;
  const float* A0 = X + mbase * Dd;
  const float* B0 = Wi + nbase;

  const int arow = tid >> 2;
  const int acol = (tid & 3) << 2;
  const int brow = tid >> 5;
  const int bcol = (tid & 31) << 2;
  const int tx = tid & 15;
  const int ty = tid >> 4;

  ull acc[8][4];
#pragma unroll
  for (int i = 0; i < 8; i++)
#pragma unroll
    for (int j = 0; j < 4; j++) acc[i][j] = 0ull;

  for (int k0 = 0; k0 < Dd; k0 += 16) {
#pragma unroll
    for (int i = 0; i < 2; i++) {
      float4 a = *(const float4*)(A0 + (size_t)(arow + i * 64) * Dd + k0 + acol);
      As[acol + 0][arow + i * 64] = a.x;
      As[acol + 1][arow + i * 64] = a.y;
      As[acol + 2][arow + i * 64] = a.z;
      As[acol + 3][arow + i * 64] = a.w;
    }
#pragma unroll
    for (int i = 0; i < 2; i++) {
      *(float4*)&Bs[brow + i * 8][bcol] =
          *(const float4*)(B0 + (size_t)(k0 + brow + i * 8) * Gg + bcol);
    }
    __syncthreads();
#pragma unroll
    for (int k = 0; k < 16; k++) {
      float ra[8];
      *(float4*)&ra[0] = *(const float4*)&As[k][ty * 8];
      *(float4*)&ra[4] = *(const float4*)&As[k][ty * 8 + 4];
      ulonglong2 rb0 = *(const ulonglong2*)&Bs[k][tx * 8];
      ulonglong2 rb1 = *(const ulonglong2*)&Bs[k][tx * 8 + 4];
      ull ra2[8];
#pragma unroll
      for (int i = 0; i < 8; i++) ra2[i] = pack_dup(ra[i]);
#pragma unroll
      for (int i = 0; i < 8; i++) {
        FMA2(acc[i][0], ra2[i], rb0.x);
        FMA2(acc[i][1], ra2[i], rb0.y);
        FMA2(acc[i][2], ra2[i], rb1.x);
        FMA2(acc[i][3], ra2[i], rb1.y);
      }
    }
    __syncthreads();
  }

  float* C = g_xg + (mbase + (size_t)ty * 8) * Gg + nbase + tx * 8;
#pragma unroll
  for (int i = 0; i < 8; i++) {
    float2 p0 = unpack2(acc[i][0]);
    float2 p1 = unpack2(acc[i][1]);
    float2 p2 = unpack2(acc[i][2]);
    float2 p3 = unpack2(acc[i][3]);
    *(float4*)(C + (size_t)i * Gg) = make_float4(p0.x, p0.y, p1.x, p1.y);
    *(float4*)(C + (size_t)i * Gg + 4) = make_float4(p2.x, p2.y, p3.x, p3.y);
  }
}

// ---------------------------------------------------------------------------
// Kernel B: persistent cluster LSTM recurrence.
// 16 clusters x 8 CTAs, 256 threads. CTA r owns gate cols {g*256+r*32..+32}.
// GEMM: thread (ks=tid>>5, cg=tid&31) -> 4 gate-aligned cols x 8 batches
//   over k in [ks*32, ks*32+32). Crossbar traffic 1536 wf-cyc < 2048 FMA floor.
// Update: thread (b=tid>>5, jj=tid&31) owns ONE h element; sums 8 k-partials
//   per gate, xg read via direct LDG issued at step top (hidden under GEMM).
// Exchange: plain DSMEM stores to all 8 ranks + split barrier.cluster
//   arrive/wait (one rendezvous per step; no mbarrier tx storm).
// ---------------------------------------------------------------------------

// SMEM float offsets
#define WHS_OFF 0        // [64 kc][128 col][4]   = 32768 (128 KB)
#define HB_OFF 32768     // [2][8 b][256 k]       =  4096 (16 KB)
#define PART_OFF 36864   // [8 ks][8 b][128 col]  =  8192 (32 KB)
#define SMEM_FLOATS 45056
#define SMEM_BYTES (SMEM_FLOATS * 4)

#define CLUSTER_ARRIVE() asm volatile("barrier.cluster.arrive.aligned;" ::: "memory")
#define CLUSTER_WAIT()   asm volatile("barrier.cluster.wait.aligned;" ::: "memory")

__device__ __forceinline__ float sigf(float x) {
  return 1.f / (1.f + __expf(-x));
}
__device__ __forceinline__ float tanhf_(float x) {
  return 2.f / (1.f + __expf(-2.f * x)) - 1.f;
}

__global__ __launch_bounds__(256, 1) __cluster_dims__(8, 1, 1)
void lstm_rec(const float* __restrict__ Wh, const float* __restrict__ bh,
              float* __restrict__ out) {
  extern __shared__ float sm[];
  float* whs = sm + WHS_OFF;
  float* hb = sm + HB_OFF;
  float* part = sm + PART_OFF;

  cg::cluster_group cluster = cg::this_cluster();
  const int r = blockIdx.x;
  const int cl = blockIdx.y;
  const int tid = threadIdx.x;

  // ---- one-time init: Wh slice [k/4][col][4], h0 = 0 ----
  for (int idx = tid; idx < 32768; idx += 256) {
    int c = idx & 127;
    int k = idx >> 7;
    int gcol = ((c >> 5) << 8) + (r << 5) + (c & 31);
    whs[((k >> 2) << 9) + (c << 2) + (k & 3)] = Wh[k * Gg + gcol];
  }
  for (int idx = tid; idx < 4096; idx += 256) hb[idx] = 0.f;

  // update-phase mapping: one h element per thread
  const int ub = tid >> 5;  // batch 0..7
  const int jj = tid & 31;  // h column within CTA slice
  const int m = (r << 5) + jj;
  float breg[4];
#pragma unroll
  for (int g = 0; g < 4; g++) breg[g] = bh[(g << 8) + m];

  // GEMM-phase mapping
  const int ks = tid >> 5;  // k-split 0..7 (32 k's = 8 kc each)
  const int cg2 = tid & 31; // col group: cols cg2 + 32g
  const int kc0 = ks << 3;

  // remote smem base pointers for h replication
  float* rank_h[2][8];
#pragma unroll
  for (int rk = 0; rk < 8; rk++) {
    rank_h[0][rk] = cluster.map_shared_rank(hb, rk);
    rank_h[1][rk] = cluster.map_shared_rank(hb + 2048, rk);
  }

  cluster.sync();  // smem init visible cluster-wide before remote writes

  float creg = 0.f;
  const size_t OUT_FIN = (size_t)Bb * Tt * Hh;
  const size_t gb = (size_t)(cl << 3) + ub;
  const float* xgp = g_xg + (gb * Tt) * Gg + m;  // + t*Gg + g*256
  float* const out_base = out + (gb << 10) * Hh + m;

  for (int t = 0; t < Tt; t++) {
    if (t) CLUSTER_WAIT();  // pairs arrive(t-1): h(t) ready, part WAR safe

    // xg for this step: 4 coalesced LDGs, consumed ~2000 cyc later
    float xr0 = __ldg(xgp + (size_t)t * Gg);
    float xr1 = __ldg(xgp + (size_t)t * Gg + 256);
    float xr2 = __ldg(xgp + (size_t)t * Gg + 512);
    float xr3 = __ldg(xgp + (size_t)t * Gg + 768);

    // ---- GEMM: part[ks][b][c] over this thread's 32-k slice, 4 cols ----
    {
      const ulonglong2* w2 = (const ulonglong2*)whs;              // [kc][128]
      const ulonglong2* h2 = (const ulonglong2*)(hb + (t & 1) * 2048);
      ull acc[8][4];
#pragma unroll
      for (int b = 0; b < 8; b++)
#pragma unroll
        for (int g = 0; g < 4; g++) acc[b][g] = 0ull;

#pragma unroll 2
      for (int kk = 0; kk < 8; kk++) {
        int kc = kc0 + kk;
        ulonglong2 w0 = w2[(kc << 7) + cg2];
        ulonglong2 w1 = w2[(kc << 7) + cg2 + 32];
        ulonglong2 wv = w2[(kc << 7) + cg2 + 64];
        ulonglong2 w3 = w2[(kc << 7) + cg2 + 96];
#pragma unroll
        for (int b = 0; b < 8; b++) {
          ulonglong2 hv = h2[(b << 6) + kc];
          FMA2(acc[b][0], hv.x, w0.x);
          FMA2(acc[b][0], hv.y, w0.y);
          FMA2(acc[b][1], hv.x, w1.x);
          FMA2(acc[b][1], hv.y, w1.y);
          FMA2(acc[b][2], hv.x, wv.x);
          FMA2(acc[b][2], hv.y, wv.y);
          FMA2(acc[b][3], hv.x, w3.x);
          FMA2(acc[b][3], hv.y, w3.y);
        }
      }
#pragma unroll
      for (int b = 0; b < 8; b++)
#pragma unroll
        for (int g = 0; g < 4; g++) {
          float2 s = unpack2(acc[b][g]);
          part[(ks << 10) + (b << 7) + (g << 5) + cg2] = s.x + s.y;
        }
    }

    __syncthreads();  // part RAW

    // ---- update: reduce 8 partials per gate, nonlinearity, push ----
    {
      float gv[4] = {xr0 + breg[0], xr1 + breg[1], xr2 + breg[2],
                     xr3 + breg[3]};
#pragma unroll
      for (int s = 0; s < 8; s++) {
        const float* pc = part + (s << 10) + (ub << 7) + jj;
        gv[0] += pc[0];
        gv[1] += pc[32];
        gv[2] += pc[64];
        gv[3] += pc[96];
      }
      float iv = sigf(gv[0]);
      float fv = sigf(gv[1]);
      float zv = tanhf_(gv[2]);
      float ov = sigf(gv[3]);
      float cnew = fv * creg + iv * zv;
      creg = cnew;
      float hv = ov * tanhf_(cnew);

      if (t + 1 < Tt) {
        int qn = (t + 1) & 1;
        int off = (ub << 8) + m;
#pragma unroll
        for (int i = 0; i < 8; i++) {
          int rk = (i + tid) & 7;  // stagger fabric traffic
          rank_h[qn][rk][off] = hv;
        }
        CLUSTER_ARRIVE();  // release: pushes visible at wait(t+1)
      }

      // global stores off the sync path
      out_base[(size_t)t * Hh] = hv;
      if (t == Tt - 1) {
        out[OUT_FIN + gb * Hh + m] = cnew;
        out[OUT_FIN + (size_t)Bb * Hh + gb * Hh + m] = hv;
      }
    }
  }

  cluster.sync();  // no CTA exits while peer traffic could be in flight
}

// ---------------------------------------------------------------------------
extern "C" void kernel_launch(void* const* d_in, const int* in_sizes, int n_in,
                              void* d_out, int out_size) {
  const float* x = (const float*)d_in[0];    // [B, T, D]
  const float* Wi = (const float*)d_in[1];   // [D, 4H]
  const float* Wh = (const float*)d_in[2];   // [H, 4H]
  const float* bh = (const float*)d_in[3];   // [4H]
  float* out = (float*)d_out;                // outputs | c_fin | h_fin

  dim3 gA(Gg / 128, (Bb * Tt) / 128);  // (8, 1024)
  xg_gemm<<<gA, 256>>>(x, Wi);

  cudaFuncSetAttribute(lstm_rec, cudaFuncAttributeMaxDynamicSharedMemorySize,
                       SMEM_BYTES);
  lstm_rec<<<dim3(8, 16), 256, SMEM_BYTES>>>(Wh, bh, out);
}